// round 1
// baseline (speedup 1.0000x reference)
#include <cuda_runtime.h>
#include <cstdint>

// TropicalConv2D: out[b,c,h,w] = max_{di,dj in [-2,2]} x[b,c,h+di,w+dj] + kflip[c,di+2,dj+2]
// with kflip[a,b] = kernel[c, 0, 4-a, 4-b], OOB = -inf.
// Fixed shapes: B=8, C=32, H=W=224, K=5, stride=1, pad=2, dil=1.

#define HH 224
#define WW 224
#define CC 32
#define BB 8

__device__ __forceinline__ float neg_inf() { return __int_as_float(0xff800000); }

// Apply all taps contributed by input-row r (of the 8-row window) to the 4x4 acc.
// xr[2..9] hold input columns w0-2 .. w0+5 (xr has 12 slots for the fast-path 3x float4).
__device__ __forceinline__ void apply_row_taps(const int r, const float xr[12],
                                               const float wf[25], float acc[4][4]) {
#pragma unroll
    for (int oh = 0; oh < 4; ++oh) {
        const int a = r - oh;              // kernel row index (0..4) if valid
        if (a >= 0 && a <= 4) {
#pragma unroll
            for (int j = 0; j < 5; ++j) {
                const float wv = wf[a * 5 + j];
#pragma unroll
                for (int ow = 0; ow < 4; ++ow) {
                    acc[oh][ow] = fmaxf(acc[oh][ow], xr[2 + ow + j] + wv);
                }
            }
        }
    }
}

extern "C" __global__ void __launch_bounds__(224)
tropical_conv2d_kernel(const float* __restrict__ x,
                       const float* __restrict__ kern,
                       float* __restrict__ out) {
    const int tx = threadIdx.x;                 // 0..27  -> w-tile within block
    const int ty = threadIdx.y;                 // 0..7   -> h-tile within block
    const int w0 = (blockIdx.x * 28 + tx) * 4;  // left output col of this thread's 4x4 tile
    const int h0 = (blockIdx.y * 8 + ty) * 4;   // top output row
    const int plane = blockIdx.z;               // b*C + c
    const int c = plane & (CC - 1);

    // Flipped per-channel weights: wf[a*5+j] = kernel[c*25 + (4-a)*5 + (4-j)] = kernel[c*25 + 24 - (a*5+j)]
    float wf[25];
    const float* kc = kern + c * 25;
#pragma unroll
    for (int t = 0; t < 25; ++t) wf[t] = __ldg(kc + (24 - t));

    const float* xp = x + (size_t)plane * (HH * WW);

    float acc[4][4];
#pragma unroll
    for (int i = 0; i < 4; ++i)
#pragma unroll
        for (int j = 0; j < 4; ++j) acc[i][j] = neg_inf();

    // Fast path: entire 8x12 load window (rows h0-2..h0+5, cols w0-4..w0+7) in-bounds.
    const bool fast = (w0 >= 4) && (w0 <= WW - 8) && (h0 >= 2) && (h0 <= HH - 6);

    if (fast) {
#pragma unroll
        for (int r = 0; r < 8; ++r) {
            const int y = h0 - 2 + r;
            const float4* p = reinterpret_cast<const float4*>(xp + y * WW + (w0 - 4));
            const float4 q0 = __ldg(p + 0);
            const float4 q1 = __ldg(p + 1);
            const float4 q2 = __ldg(p + 2);
            const float xr[12] = {q0.x, q0.y, q0.z, q0.w,
                                  q1.x, q1.y, q1.z, q1.w,
                                  q2.x, q2.y, q2.z, q2.w};
            apply_row_taps(r, xr, wf, acc);
        }
    } else {
#pragma unroll
        for (int r = 0; r < 8; ++r) {
            const int y = h0 - 2 + r;
            const bool rowOK = (y >= 0) && (y < HH);
            float xr[12];
            xr[0] = xr[1] = xr[10] = xr[11] = neg_inf();
#pragma unroll
            for (int k = 0; k < 8; ++k) {
                const int col = w0 - 2 + k;
                const bool ok = rowOK && (col >= 0) && (col < WW);
                xr[2 + k] = ok ? __ldg(xp + y * WW + col) : neg_inf();
            }
            apply_row_taps(r, xr, wf, acc);
        }
    }

    // Store 4 rows x 4 cols (float4, w0 is 16B-aligned).
    float* op = out + (size_t)plane * (HH * WW);
#pragma unroll
    for (int oh = 0; oh < 4; ++oh) {
        float4 v = make_float4(acc[oh][0], acc[oh][1], acc[oh][2], acc[oh][3]);
        *reinterpret_cast<float4*>(op + (h0 + oh) * WW + w0) = v;
    }
}

extern "C" void kernel_launch(void* const* d_in, const int* in_sizes, int n_in,
                              void* d_out, int out_size) {
    const float* x = (const float*)d_in[0];
    const float* kern = (const float*)d_in[1];
    // d_in[2..4] = stride/padding/dilation (fixed: 1, 2, 1)
    float* out = (float*)d_out;

    dim3 block(28, 8, 1);          // 224 threads, each 4x4 outputs -> 112x32 block tile
    dim3 grid(2, 7, BB * CC);      // 2*112=224 cols, 7*32=224 rows, 256 planes
    tropical_conv2d_kernel<<<grid, block>>>(x, kern, out);
}

// round 3
// speedup vs baseline: 1.0975x; 1.0975x over previous
#include <cuda_runtime.h>
#include <cstdint>

// TropicalConv2D: out[b,c,h,w] = max_{di,dj in [-2,2]} x[b,c,h+di,w+dj] + kflip[c,di+2,dj+2]
// kflip[a,b] = kernel[c,0,4-a,4-b], OOB = -inf.
// Fixed: B=8, C=32, H=W=224, K=5, stride=1, pad=2, dil=1.

#define HH 224
#define WW 224
#define CC 32
#define BB 8

// Block tile: 112 (w) x 32 (h) outputs, 28x8 threads, 4x4 outputs/thread.
// Staged input window: 36 rows x 120 cols (halo: 2 top/bottom, 4 left / 4 right for alignment).
#define SROWS 36
#define SCOLS 120
#define SCHUNKS (SROWS * (SCOLS / 4))   // 1080 float4 chunks

__device__ __forceinline__ float neg_inf() { return __int_as_float(0xff800000); }

__device__ __forceinline__ void apply_row_taps(const int r, const float xr[12],
                                               const float wf[25], float acc[4][4]) {
#pragma unroll
    for (int oh = 0; oh < 4; ++oh) {
        const int a = r - oh;              // kernel row index (0..4) if valid
        if (a >= 0 && a <= 4) {
#pragma unroll
            for (int j = 0; j < 5; ++j) {
                const float wv = wf[a * 5 + j];
#pragma unroll
                for (int ow = 0; ow < 4; ++ow) {
                    // window offset 2+ow+j = global col w0 - 2 + (ow + j)   [halo-4 origin]
                    acc[oh][ow] = fmaxf(acc[oh][ow], xr[2 + ow + j] + wv);
                }
            }
        }
    }
}

extern "C" __global__ void __launch_bounds__(224)
tropical_conv2d_kernel(const float* __restrict__ x,
                       const float* __restrict__ kern,
                       float* __restrict__ out) {
    __shared__ float stile[SROWS * SCOLS];

    const int tx = threadIdx.x;                 // 0..27
    const int ty = threadIdx.y;                 // 0..7
    const int tid = ty * 28 + tx;               // 0..223
    const int plane = blockIdx.z;               // b*C + c
    const int c = plane & (CC - 1);

    const float* xp = x + (size_t)plane * (HH * WW);

    // ---- Stage the 36x120 window into smem with -inf padding ----
    // Window origin: row by*32 - 2, col bx*112 - 4. Every float4 chunk is
    // fully in-bounds or fully OOB (col base and W both ≡ 0 mod 4).
    {
        const int row0 = blockIdx.y * 32 - 2;
        const int col0 = blockIdx.x * 112 - 4;
        const float NI = neg_inf();
        for (int i = tid; i < SCHUNKS; i += 224) {
            const int ry = i / (SCOLS / 4);
            const int c4 = i - ry * (SCOLS / 4);
            const int gy = row0 + ry;
            const int gc = col0 + c4 * 4;
            float4 v = make_float4(NI, NI, NI, NI);
            if (gy >= 0 && gy < HH && gc >= 0 && gc < WW) {
                v = *reinterpret_cast<const float4*>(xp + gy * WW + gc);
            }
            *reinterpret_cast<float4*>(&stile[ry * SCOLS + c4 * 4]) = v;
        }
    }

    // Flipped per-channel weights (uniform across warp): wf[t] = kernel[c*25 + 24 - t]
    float wf[25];
    const float* kc = kern + c * 25;
#pragma unroll
    for (int t = 0; t < 25; ++t) wf[t] = __ldg(kc + (24 - t));

    __syncthreads();

    float acc[4][4];
#pragma unroll
    for (int i = 0; i < 4; ++i)
#pragma unroll
        for (int j = 0; j < 4; ++j) acc[i][j] = neg_inf();

    // Thread's window inside smem: rows ty*4 .. ty*4+7, cols tx*4 .. tx*4+11
    // (window col tx*4 + k = global col w0 - 4 + k).
    const float* sb = &stile[(ty * 4) * SCOLS + tx * 4];
#pragma unroll
    for (int r = 0; r < 8; ++r) {
        const float4 q0 = *reinterpret_cast<const float4*>(sb + r * SCOLS + 0);
        const float4 q1 = *reinterpret_cast<const float4*>(sb + r * SCOLS + 4);
        const float4 q2 = *reinterpret_cast<const float4*>(sb + r * SCOLS + 8);
        const float xr[12] = {q0.x, q0.y, q0.z, q0.w,
                              q1.x, q1.y, q1.z, q1.w,
                              q2.x, q2.y, q2.z, q2.w};
        apply_row_taps(r, xr, wf, acc);
    }

    // Store 4 rows x 4 cols (float4-aligned).
    const int w0 = blockIdx.x * 112 + tx * 4;
    const int h0 = blockIdx.y * 32 + ty * 4;
    float* op = out + (size_t)plane * (HH * WW);
#pragma unroll
    for (int oh = 0; oh < 4; ++oh) {
        float4 v = make_float4(acc[oh][0], acc[oh][1], acc[oh][2], acc[oh][3]);
        *reinterpret_cast<float4*>(op + (h0 + oh) * WW + w0) = v;
    }
}

extern "C" void kernel_launch(void* const* d_in, const int* in_sizes, int n_in,
                              void* d_out, int out_size) {
    const float* x = (const float*)d_in[0];
    const float* kern = (const float*)d_in[1];
    float* out = (float*)d_out;

    dim3 block(28, 8, 1);          // 224 threads, 4x4 outputs each -> 112x32 tile
    dim3 grid(2, 7, BB * CC);      // 224 cols, 224 rows, 256 planes
    tropical_conv2d_kernel<<<grid, block>>>(x, kern, out);
}

// round 6
// speedup vs baseline: 1.5207x; 1.3856x over previous
#include <cuda_runtime.h>
#include <cstdint>

// TropicalConv2D: out[b,c,h,w] = max_{di,dj in [-2,2]} x[b,c,h+di,w+dj] + kflip[c,di+2,dj+2]
// kflip[a,b] = kernel[c,0,4-a,4-b], OOB = -inf.
// Fixed: B=8, C=32, H=W=224, K=5, stride=1, pad=2, dil=1.

#define HH 224
#define WW 224
#define CC 32
#define BB 8

// Block tile: 112 (w) x 32 (h) outputs, 28x8 threads, 4x4 outputs/thread.
// Staged input window: 36 rows x 120 cols (halo: 2 top/bottom, 4 left/right for alignment).
#define SROWS 36
#define SCOLS 120
#define SCHUNKS (SROWS * (SCOLS / 4))   // 1080 float4 chunks

__device__ __forceinline__ float neg_inf() { return __int_as_float(0xff800000); }

__device__ __forceinline__ void apply_row_taps(const int r, const float xr[12],
                                               const float wf[25], float acc[4][4]) {
#pragma unroll
    for (int oh = 0; oh < 4; ++oh) {
        const int a = r - oh;              // kernel row index (0..4) if valid
        if (a >= 0 && a <= 4) {
#pragma unroll
            for (int j = 0; j < 5; ++j) {
                const float wv = wf[a * 5 + j];
#pragma unroll
                for (int ow = 0; ow < 4; ++ow) {
                    // window offset 2+ow+j = global col w0 - 2 + (ow + j)   [halo-4 origin]
                    acc[oh][ow] = fmaxf(acc[oh][ow], xr[2 + ow + j] + wv);
                }
            }
        }
    }
}

extern "C" __global__ void __launch_bounds__(224, 3)
tropical_conv2d_kernel(const float* __restrict__ x,
                       const float* __restrict__ kern,
                       float* __restrict__ out) {
    __shared__ float stile[SROWS * SCOLS];

    const int tx = threadIdx.x;                 // 0..27
    const int ty = threadIdx.y;                 // 0..7
    const int tid = ty * 28 + tx;               // 0..223
    const int plane = blockIdx.z;               // b*C + c
    const int c = plane & (CC - 1);

    const float* xp = x + (size_t)plane * (HH * WW);

    // Issue flipped per-channel weight loads early (uniform across block):
    // wf[t] = kernel[c*25 + 24 - t]
    float wf[25];
    const float* kc = kern + c * 25;
#pragma unroll
    for (int t = 0; t < 25; ++t) wf[t] = __ldg(kc + (24 - t));

    // ---- Stage the 36x120 window into smem with -inf padding ----
    // Window origin: row by*32 - 2, col bx*112 - 4. Every float4 chunk is
    // fully in-bounds or fully OOB (col base and W both ≡ 0 mod 4).
    {
        const int row0 = blockIdx.y * 32 - 2;
        const int col0 = blockIdx.x * 112 - 4;
        const float NI = neg_inf();
#pragma unroll
        for (int it = 0; it < 5; ++it) {
            const int i = tid + it * 224;
            if (it < 4 || i < SCHUNKS) {   // iterations 0..3 always in range (4*224=896 < 1080)
                const int ry = i / (SCOLS / 4);
                const int c4 = i - ry * (SCOLS / 4);
                const int gy = row0 + ry;
                const int gc = col0 + c4 * 4;
                float4 v = make_float4(NI, NI, NI, NI);
                if (gy >= 0 && gy < HH && gc >= 0 && gc < WW) {
                    v = *reinterpret_cast<const float4*>(xp + gy * WW + gc);
                }
                *reinterpret_cast<float4*>(&stile[ry * SCOLS + c4 * 4]) = v;
            }
        }
    }

    __syncthreads();

    float acc[4][4];
#pragma unroll
    for (int i = 0; i < 4; ++i)
#pragma unroll
        for (int j = 0; j < 4; ++j) acc[i][j] = neg_inf();

    // Thread's window inside smem: rows ty*4 .. ty*4+7, cols tx*4 .. tx*4+11
    // (window col tx*4 + k = global col w0 - 4 + k).
    const float* sb = &stile[(ty * 4) * SCOLS + tx * 4];
#pragma unroll
    for (int r = 0; r < 8; ++r) {
        const float4 q0 = *reinterpret_cast<const float4*>(sb + r * SCOLS + 0);
        const float4 q1 = *reinterpret_cast<const float4*>(sb + r * SCOLS + 4);
        const float4 q2 = *reinterpret_cast<const float4*>(sb + r * SCOLS + 8);
        const float xr[12] = {q0.x, q0.y, q0.z, q0.w,
                              q1.x, q1.y, q1.z, q1.w,
                              q2.x, q2.y, q2.z, q2.w};
        apply_row_taps(r, xr, wf, acc);
    }

    // Store 4 rows x 4 cols (float4-aligned).
    const int w0 = blockIdx.x * 112 + tx * 4;
    const int h0 = blockIdx.y * 32 + ty * 4;
    float* op = out + (size_t)plane * (HH * WW);
#pragma unroll
    for (int oh = 0; oh < 4; ++oh) {
        float4 v = make_float4(acc[oh][0], acc[oh][1], acc[oh][2], acc[oh][3]);
        *reinterpret_cast<float4*>(op + (h0 + oh) * WW + w0) = v;
    }
}

extern "C" void kernel_launch(void* const* d_in, const int* in_sizes, int n_in,
                              void* d_out, int out_size) {
    const float* x = (const float*)d_in[0];
    const float* kern = (const float*)d_in[1];
    float* out = (float*)d_out;

    dim3 block(28, 8, 1);          // 224 threads, 4x4 outputs each -> 112x32 tile
    dim3 grid(2, 7, BB * CC);      // 224 cols, 224 rows, 256 planes
    tropical_conv2d_kernel<<<grid, block>>>(x, kern, out);
}

// round 7
// speedup vs baseline: 1.5644x; 1.0287x over previous
#include <cuda_runtime.h>
#include <cstdint>

// TropicalConv2D: out[b,c,h,w] = max_{di,dj in [-2,2]} x[b,c,h+di,w+dj] + kflip[c,di+2,dj+2]
// kflip[a,b] = kernel[c,0,4-a,4-b], OOB = -inf.
// Fixed: B=8, C=32, H=W=224, K=5, stride=1, pad=2, dil=1.

#define HH 224
#define WW 224
#define CC 32
#define BB 8

// Block tile: 112 (w) x 32 (h) outputs, 28x8 threads, 4x4 outputs/thread.
// Staged window: 36 rows x 116 cols (halo 2 on all sides). Origin col ≡ 2 mod 4,
// so staging uses float2 chunks (8B-aligned in gmem; even cols + even W ⇒ each
// chunk fully in-bounds or fully OOB).
#define SROWS 36
#define SCOLS 116
#define SCH2 (SROWS * (SCOLS / 2))   // 2088 float2 chunks

__device__ __forceinline__ float neg_inf() { return __int_as_float(0xff800000); }

__device__ __forceinline__ void apply_row_taps(const int r, const float xr[8],
                                               const float wf[25], float acc[4][4]) {
#pragma unroll
    for (int oh = 0; oh < 4; ++oh) {
        const int a = r - oh;              // kernel row index (0..4) if valid
        if (a >= 0 && a <= 4) {
#pragma unroll
            for (int j = 0; j < 5; ++j) {
                const float wv = wf[a * 5 + j];
#pragma unroll
                for (int ow = 0; ow < 4; ++ow) {
                    // xr[k] = global col w0 - 2 + k ; taps need k = ow + j in 0..7
                    acc[oh][ow] = fmaxf(acc[oh][ow], xr[ow + j] + wv);
                }
            }
        }
    }
}

extern "C" __global__ void __launch_bounds__(224, 4)
tropical_conv2d_kernel(const float* __restrict__ x,
                       const float* __restrict__ kern,
                       float* __restrict__ out) {
    __shared__ float stile[SROWS * SCOLS];

    const int tx = threadIdx.x;                 // 0..27
    const int ty = threadIdx.y;                 // 0..7
    const int tid = ty * 28 + tx;               // 0..223
    const int plane = blockIdx.z;               // b*C + c
    const int c = plane & (CC - 1);

    const float* xp = x + (size_t)plane * (HH * WW);

    // Flipped per-channel weights (uniform across block): wf[t] = kernel[c*25 + 24 - t]
    float wf[25];
    const float* kc = kern + c * 25;
#pragma unroll
    for (int t = 0; t < 25; ++t) wf[t] = __ldg(kc + (24 - t));

    // ---- Stage the 36x116 window into smem with -inf padding (float2 chunks) ----
    {
        const int row0 = blockIdx.y * 32 - 2;
        const int col0 = blockIdx.x * 112 - 2;
        const float NI = neg_inf();
#pragma unroll
        for (int it = 0; it < 10; ++it) {
            const int i = tid + it * 224;
            if (it < 9 || i < SCH2) {      // 9*224=2016 < 2088; last iter partial
                const int ry = i / (SCOLS / 2);
                const int c2 = i - ry * (SCOLS / 2);
                const int gy = row0 + ry;
                const int gc = col0 + c2 * 2;   // even ⇒ chunk fully in or out
                float2 v = make_float2(NI, NI);
                if (gy >= 0 && gy < HH && gc >= 0 && gc < WW) {
                    v = *reinterpret_cast<const float2*>(xp + gy * WW + gc);
                }
                *reinterpret_cast<float2*>(&stile[ry * SCOLS + c2 * 2]) = v;
            }
        }
    }

    __syncthreads();

    float acc[4][4];
#pragma unroll
    for (int i = 0; i < 4; ++i)
#pragma unroll
        for (int j = 0; j < 4; ++j) acc[i][j] = neg_inf();

    // Thread window in smem: rows ty*4 .. ty*4+7, cols tx*4 .. tx*4+7
    // (window col tx*4 + k = global col w0 - 2 + k). 16B-aligned: 116*4=464≡0 mod 16.
    const float* sb = &stile[(ty * 4) * SCOLS + tx * 4];
#pragma unroll
    for (int r = 0; r < 8; ++r) {
        const float4 q0 = *reinterpret_cast<const float4*>(sb + r * SCOLS + 0);
        const float4 q1 = *reinterpret_cast<const float4*>(sb + r * SCOLS + 4);
        const float xr[8] = {q0.x, q0.y, q0.z, q0.w,
                             q1.x, q1.y, q1.z, q1.w};
        apply_row_taps(r, xr, wf, acc);
    }

    // Store 4 rows x 4 cols (float4-aligned).
    const int w0 = blockIdx.x * 112 + tx * 4;
    const int h0 = blockIdx.y * 32 + ty * 4;
    float* op = out + (size_t)plane * (HH * WW);
#pragma unroll
    for (int oh = 0; oh < 4; ++oh) {
        float4 v = make_float4(acc[oh][0], acc[oh][1], acc[oh][2], acc[oh][3]);
        *reinterpret_cast<float4*>(op + (h0 + oh) * WW + w0) = v;
    }
}

extern "C" void kernel_launch(void* const* d_in, const int* in_sizes, int n_in,
                              void* d_out, int out_size) {
    const float* x = (const float*)d_in[0];
    const float* kern = (const float*)d_in[1];
    float* out = (float*)d_out;

    dim3 block(28, 8, 1);          // 224 threads, 4x4 outputs each -> 112x32 tile
    dim3 grid(2, 7, BB * CC);      // 224 cols, 224 rows, 256 planes
    tropical_conv2d_kernel<<<grid, block>>>(x, kern, out);
}

// round 8
// speedup vs baseline: 1.6231x; 1.0375x over previous
#include <cuda_runtime.h>
#include <cstdint>

// TropicalConv2D: out[b,c,h,w] = max_{di,dj in [-2,2]} x[b,c,h+di,w+dj] + kflip[c,di+2,dj+2]
// kflip[a,b] = kernel[c,0,4-a,4-b], OOB = -inf.
// Fixed: B=8, C=32, H=W=224, K=5, stride=1, pad=2, dil=1.

#define HH 224
#define WW 224
#define CC 32
#define BB 8

// Block tile: 112 (w) x 32 (h) outputs, 28x8 threads, 4x4 outputs/thread.
// Window: 36 rows x cols [w0blk-2, w0blk+114) staged in smem, row stride 120.
// Staged via float4 gmem chunks at global col ≡ 0 mod 4 (col0 = w0blk-4), written
// to smem at col (chunk*4 - 2): 8B-aligned -> two float2 stores. A 4-float guard
// in front absorbs the s=-2 writes; cols 116..119 of each row absorb the tail.
#define SROWS 36
#define SCOLW 120
#define NCHUNK (SROWS * 30)   // 1080 float4 chunks

__device__ __forceinline__ float neg_inf() { return __int_as_float(0xff800000); }

extern "C" __global__ void __launch_bounds__(224, 4)
tropical_conv2d_kernel(const float* __restrict__ x,
                       const float* __restrict__ kern,
                       float* __restrict__ out) {
    __shared__ __align__(16) float smem_raw[4 + SROWS * SCOLW];
    float* const stile = smem_raw + 4;   // 16B-aligned base; stile[-2] is valid

    const int tx = threadIdx.x;                 // 0..27
    const int ty = threadIdx.y;                 // 0..7
    const int tid = ty * 28 + tx;               // 0..223
    const int plane = blockIdx.z;               // b*C + c
    const int c = plane & (CC - 1);

    const float* xp = x + (size_t)plane * (HH * WW);

    // Flipped per-channel weights (uniform across block): wf[t] = kernel[c*25 + 24 - t]
    float wf[25];
    const float* kc = kern + c * 25;
#pragma unroll
    for (int t = 0; t < 25; ++t) wf[t] = __ldg(kc + (24 - t));

    // ---- Stage window into smem with -inf padding (branchless, float4 loads) ----
    {
        const int row0 = blockIdx.y * 32 - 2;
        const int col0 = blockIdx.x * 112 - 4;   // ≡ 0 mod 4 -> aligned gmem float4
        const float NI = neg_inf();
#pragma unroll
        for (int it = 0; it < 5; ++it) {
            const int i = tid + it * 224;
            if (it < 4 || i < NCHUNK) {          // 4*224=896 < 1080; last iter partial
                const int ry = i / 30;
                const int c4 = i - ry * 30;
                const int gy = row0 + ry;
                const int gc = col0 + c4 * 4;
                // Chunk is fully in-bounds or fully OOB (gc ≡ 0 mod 4, W ≡ 0 mod 4).
                const int cy = min(max(gy, 0), HH - 1);
                const int cc = min(max(gc, 0), WW - 4);
                const float4 v = *reinterpret_cast<const float4*>(xp + cy * WW + cc);
                const bool ok = ((unsigned)gy < (unsigned)HH) && ((unsigned)gc < (unsigned)WW);
                float2 lo, hi;
                lo.x = ok ? v.x : NI;  lo.y = ok ? v.y : NI;
                hi.x = ok ? v.z : NI;  hi.y = ok ? v.w : NI;
                float* dst = &stile[ry * SCOLW + c4 * 4 - 2];
                *reinterpret_cast<float2*>(dst) = lo;
                *reinterpret_cast<float2*>(dst + 2) = hi;
            }
        }
    }

    __syncthreads();

    // acc initialized at first tap (a==0, j==0) -> no -inf init, 16 fewer FMNMX.
    float acc[4][4];

    // Thread window: smem rows ty*4 .. ty*4+7, cols tx*4 .. tx*4+7
    // (smem col s = global col w0blk - 2 + s). Reads are 16B-aligned.
    const float* sb = &stile[(ty * 4) * SCOLW + tx * 4];
#pragma unroll
    for (int r = 0; r < 8; ++r) {
        const float4 q0 = *reinterpret_cast<const float4*>(sb + r * SCOLW + 0);
        const float4 q1 = *reinterpret_cast<const float4*>(sb + r * SCOLW + 4);
        const float xr[8] = {q0.x, q0.y, q0.z, q0.w,
                             q1.x, q1.y, q1.z, q1.w};
#pragma unroll
        for (int oh = 0; oh < 4; ++oh) {
            const int a = r - oh;          // kernel row (compile-time per unrolled iter)
            if (a >= 0 && a <= 4) {
#pragma unroll
                for (int j = 0; j < 5; ++j) {
                    const float wv = wf[a * 5 + j];
#pragma unroll
                    for (int ow = 0; ow < 4; ++ow) {
                        const float s = xr[ow + j] + wv;
                        if (a == 0 && j == 0)
                            acc[oh][ow] = s;                       // first touch
                        else
                            acc[oh][ow] = fmaxf(acc[oh][ow], s);
                    }
                }
            }
        }
    }

    // Store 4 rows x 4 cols (float4-aligned).
    const int w0 = blockIdx.x * 112 + tx * 4;
    const int h0 = blockIdx.y * 32 + ty * 4;
    float* op = out + (size_t)plane * (HH * WW);
#pragma unroll
    for (int oh = 0; oh < 4; ++oh) {
        float4 v = make_float4(acc[oh][0], acc[oh][1], acc[oh][2], acc[oh][3]);
        *reinterpret_cast<float4*>(op + (h0 + oh) * WW + w0) = v;
    }
}

extern "C" void kernel_launch(void* const* d_in, const int* in_sizes, int n_in,
                              void* d_out, int out_size) {
    const float* x = (const float*)d_in[0];
    const float* kern = (const float*)d_in[1];
    float* out = (float*)d_out;

    dim3 block(28, 8, 1);          // 224 threads, 4x4 outputs each -> 112x32 tile
    dim3 grid(2, 7, BB * CC);      // 224 cols, 224 rows, 256 planes
    tropical_conv2d_kernel<<<grid, block>>>(x, kern, out);
}